// round 9
// baseline (speedup 1.0000x reference)
#include <cuda_runtime.h>

#define LL    128
#define NANG  120
#define TB    128
#define TX    16      // CTA px extent
#define TY    8       // CTA py extent
#define ZC    32      // z per thread
#define ROWS  24      // staged rows (need <=19 for 16x8 tile)
#define RS    36      // smem row stride in floats
#define NST   6       // staging loads per thread (ROWS*ZC/TB)

typedef unsigned long long u64t;

__device__ __forceinline__ u64t pack2(float x, float y) {
    u64t r;
    asm("mov.b64 %0, {%1, %2};" : "=l"(r) : "f"(x), "f"(y));
    return r;
}
__device__ __forceinline__ void ffma2(u64t &acc, u64t v, u64t w) {
    asm("fma.rn.f32x2 %0, %1, %2, %0;" : "+l"(acc) : "l"(v), "l"(w));
}
__device__ __forceinline__ void unpack2(u64t v, float &x, float &y) {
    asm("mov.b64 {%0, %1}, %2;" : "=f"(x), "=f"(y) : "l"(v));
}
__device__ __forceinline__ void lds2(u64t &a, u64t &b, unsigned addr) {
    asm volatile("ld.shared.v2.u64 {%0, %1}, [%2];" : "=l"(a), "=l"(b) : "r"(addr));
}

// validity-weighted tap sum along one axis (replaces all bounds predicates)
__device__ __forceinline__ float gfun(float t) {
    return fmaxf(0.0f, fminf(fminf(t + 1.0f, 128.0f - t), 1.0f));
}

// zero-padded staging (OOB rows -> 0): y-taps need no bounds handling
__device__ __forceinline__ void ldg6z(float r[NST], const float * __restrict__ img_a,
                                      int ymin, int rbase, int z) {
    #pragma unroll
    for (int k = 0; k < NST; ++k) {
        int gy = ymin + rbase + 4 * k;
        r[k] = 0.0f;
        if ((unsigned)gy < (unsigned)LL) r[k] = __ldg(img_a + gy * LL + z);
    }
}
__device__ __forceinline__ void sts6(float *dst, const float r[NST], int rbase, int z) {
    #pragma unroll
    for (int k = 0; k < NST; ++k) dst[(rbase + 4 * k) * RS + z] = r[k];
}

__global__ __launch_bounds__(TB, 7)
void bp_kernel(const float * __restrict__ image, const float * __restrict__ angles,
               float * __restrict__ out) {
    __shared__ float4 s_tab[NANG];     // (cos, sin, unused, ymin bits)
    __shared__ __align__(16) float s_img[2][ROWS * RS];

    const int tid = threadIdx.x;
    const int tileX0 = (blockIdx.x & 7) * TX;
    const int tileY0 = (blockIdx.x >> 3) * TY;
    const float X0f = tileX0 - 63.5f, X1f = X0f + (TX - 1);
    const float Y0f = tileY0 - 63.5f, Y1f = Y0f + (TY - 1);

    if (tid < NANG) {
        float ph = -angles[tid] * 0.017453292519943295f;
        float sv, cv;
        sincosf(ph, &sv, &cv);
        float m = fminf(-sv * X0f, -sv * X1f) + fminf(cv * Y0f, cv * Y1f) + 63.5f;
        int ym = (int)floorf(m) - 1;
        s_tab[tid] = make_float4(cv, sv, 0.0f, __int_as_float(ym));
    }

    const int z0 = blockIdx.y * ZC;
    const int b  = blockIdx.z;

    const int warp = tid >> 5, lane = tid & 31;
    const int px = tileX0 + (warp & 1) * 8 + (lane & 7);
    const int py = tileY0 + (warp >> 1) * 4 + (lane >> 3);
    const float Xp = px - 63.5f, Yp = py - 63.5f;

    const float *img_b = image + (size_t)b * NANG * LL * LL + z0;
    const int zst = tid & 31, rbase = tid >> 5;   // staging: z lane, row base 0..3

    u64t acc[16];    // one pixel, 32 z
    #pragma unroll
    for (int i = 0; i < 16; ++i) acc[i] = 0ULL;
    float n1 = 0.0f;

    __syncthreads();  // s_tab ready

    const unsigned sm0 = (unsigned)__cvta_generic_to_shared(&s_img[0][0]);

    // prologue: angle 0 staged into buf0; angle 1 LDG'd into hold regs
    {
        float t[NST];
        ldg6z(t, img_b, __float_as_int(s_tab[0].w), rbase, zst);
        sts6(&s_img[0][0], t, rbase, zst);
    }
    float hold[NST];
    ldg6z(hold, img_b + (size_t)LL * LL, __float_as_int(s_tab[1].w), rbase, zst);

    for (int a = 0; a < NANG; ++a) {
        __syncthreads();   // buf[a&1] staged (STS drained); readers of buf[(a+1)&1] done

        const float4 tb = s_tab[a];
        const float c = tb.x, s = tb.y;
        const int   ya = __float_as_int(tb.w);

        float sx = fmaf(c, Xp, fmaf(s, Yp, 63.5f));
        float sy = fmaf(c, Yp, fmaf(-s, Xp, 63.5f));
        float y0f = floorf(sy);
        float wy  = sy - y0f;

        float hx = gfun(sx);
        n1 = fmaf(hx, gfun(sy), n1);

        float A1 = hx * wy, A0 = hx - A1;     // rows y0, y0+1 (OOB rows are zero)
        int r0 = (int)y0f - ya;               // analytically in [1, ROWS-4]

        u64t W0 = pack2(A0, A0), W1 = pack2(A1, A1);
        unsigned addr = sm0 + (unsigned)((a & 1) * (ROWS * RS * 4))
                            + (unsigned)r0 * (RS * 4);

        #pragma unroll
        for (int q = 0; q < 8; ++q) {
            u64t p0, p1, q0, q1;
            lds2(p0, p1, addr + q * 16);
            lds2(q0, q1, addr + RS * 4 + q * 16);
            ffma2(acc[2 * q],     p0, W0);
            ffma2(acc[2 * q + 1], p1, W0);
            ffma2(acc[2 * q],     q0, W1);
            ffma2(acc[2 * q + 1], q1, W1);
        }

        // stage next: STS(a+1) from hold (LDG'd one full body ago), then LDG(a+2)
        if (a + 1 < NANG) sts6(&s_img[(a + 1) & 1][0], hold, rbase, zst);
        if (a + 2 < NANG) {
            ldg6z(hold, img_b + (size_t)(a + 2) * LL * LL,
                  __float_as_int(s_tab[a + 2].w), rbase, zst);
        }
    }

    // epilogue: out = obj / (norm + delta)
    float inv1 = 1.0f / (n1 + 1e-11f);
    float *op = out + (((size_t)b * LL + px) * LL + py) * LL + z0;
    #pragma unroll
    for (int q = 0; q < 8; ++q) {
        float ax, ay, bx, by;
        unpack2(acc[2 * q],     ax, ay);
        unpack2(acc[2 * q + 1], bx, by);
        *reinterpret_cast<float4 *>(op + q * 4) =
            make_float4(ax * inv1, ay * inv1, bx * inv1, by * inv1);
    }
}

extern "C" void kernel_launch(void *const *d_in, const int *in_sizes, int n_in,
                              void *d_out, int out_size) {
    const float *image  = (const float *)d_in[0];
    const float *angles = (const float *)d_in[1];
    float *out = (float *)d_out;
    dim3 grid(128 /* 8 x-tiles * 16 y-tiles */, LL / ZC /*4*/, 2 /*B*/);
    bp_kernel<<<grid, TB>>>(image, angles, out);
}